// round 1
// baseline (speedup 1.0000x reference)
#include <cuda_runtime.h>

// Problem constants (fixed by the reference: B,C,H,W = 8,256,128,128; CQ=C/8)
#define Bb 8
#define Cc 256
#define Hh 128
#define Ww 128
#define CQ 32
#define HW (Hh * Ww)

// Scratch for the general (gamma != 0) path. __device__ globals are the
// sanctioned allocation-free scratch mechanism.
__device__ float g_q[Bb * CQ * HW];   // 16.8 MB
__device__ float g_k[Bb * CQ * HW];   // 16.8 MB
__device__ float g_v[Bb * Cc * HW];   // 134 MB

// ---------------------------------------------------------------------------
// Kernel 1: out = x (always correct contribution; final answer when gamma==0,
// overwritten by attn_kernel when gamma!=0).
// ---------------------------------------------------------------------------
__global__ void copy_kernel(const float4* __restrict__ x4,
                            float4* __restrict__ out4, int n4) {
    int i = blockIdx.x * blockDim.x + threadIdx.x;
    if (i < n4) out4[i] = x4[i];
}

// ---------------------------------------------------------------------------
// Kernel 2: q,k projections (guarded). q[b,o,h,w] = sum_c Wq[o,c] x[b,c,h,w] + bq[o]
// ---------------------------------------------------------------------------
__global__ void proj_qk_kernel(const float* __restrict__ x,
                               const float* __restrict__ Wq,
                               const float* __restrict__ bq,
                               const float* __restrict__ Wk,
                               const float* __restrict__ bk,
                               const float* __restrict__ gamma) {
    if (gamma[0] == 0.0f) return;
    const int total = Bb * CQ * HW;
    for (int idx = blockIdx.x * blockDim.x + threadIdx.x; idx < total;
         idx += gridDim.x * blockDim.x) {
        int hw = idx % HW;
        int o  = (idx / HW) % CQ;
        int b  = idx / (HW * CQ);
        float accq = bq[o];
        float acck = bk[o];
        const float* xb = x + b * Cc * HW + hw;
        for (int c = 0; c < Cc; c++) {
            float xv = xb[c * HW];
            accq = fmaf(Wq[o * Cc + c], xv, accq);
            acck = fmaf(Wk[o * Cc + c], xv, acck);
        }
        g_q[idx] = accq;
        g_k[idx] = acck;
    }
}

// ---------------------------------------------------------------------------
// Kernel 3: v projection (guarded). v[b,o,h,w] = sum_c Wv[o,c] x[b,c,h,w] + bv[o]
// ---------------------------------------------------------------------------
__global__ void proj_v_kernel(const float* __restrict__ x,
                              const float* __restrict__ Wv,
                              const float* __restrict__ bv,
                              const float* __restrict__ gamma) {
    if (gamma[0] == 0.0f) return;
    const int total = Bb * Cc * HW;
    for (int idx = blockIdx.x * blockDim.x + threadIdx.x; idx < total;
         idx += gridDim.x * blockDim.x) {
        int hw = idx % HW;
        int o  = (idx / HW) % Cc;
        int b  = idx / (HW * Cc);
        float acc = bv[o];
        const float* xb = x + b * Cc * HW + hw;
        for (int c = 0; c < Cc; c++) {
            acc = fmaf(Wv[o * Cc + c], xb[c * HW], acc);
        }
        g_v[idx] = acc;
    }
}

// ---------------------------------------------------------------------------
// Kernel 4: criss-cross attention + residual (guarded).
// For each (b,h,w): logits[0:128]  = eH[j] = sum_c q[b,c,h,w] k[b,c,j,w]  (j==h masked -inf)
//                   logits[128:256]= eW[j] = sum_c q[b,c,h,w] k[b,c,h,j]
// joint softmax over 256; outH/outW accumulate v against the two halves.
// outLR + outRL == 2.0 identically (softmax over a singleton axis).
// out = x + gamma * (outH + outW + 2).
// ---------------------------------------------------------------------------
__global__ void attn_kernel(const float* __restrict__ x,
                            float* __restrict__ out,
                            const float* __restrict__ gamma) {
    float g = gamma[0];
    if (g == 0.0f) return;

    __shared__ float qs[CQ];
    __shared__ float att[256];
    __shared__ float red[256];

    const int t = threadIdx.x;  // 256 threads
    for (int bid = blockIdx.x; bid < Bb * HW; bid += gridDim.x) {
        int w = bid % Ww;
        int h = (bid / Ww) % Hh;
        int b = bid / HW;

        if (t < CQ) qs[t] = g_q[((b * CQ + t) * Hh + h) * Ww + w];
        __syncthreads();

        float logit;
        if (t < Hh) {
            int j = t;
            float s = 0.0f;
            #pragma unroll
            for (int c = 0; c < CQ; c++)
                s = fmaf(qs[c], g_k[((b * CQ + c) * Hh + j) * Ww + w], s);
            logit = (j == h) ? __int_as_float(0xff800000) : s;  // -inf on diag
        } else {
            int j = t - Hh;
            float s = 0.0f;
            #pragma unroll
            for (int c = 0; c < CQ; c++)
                s = fmaf(qs[c], g_k[((b * CQ + c) * Hh + h) * Ww + j], s);
            logit = s;
        }

        // max-reduce over 256 logits
        red[t] = logit;
        __syncthreads();
        for (int s = 128; s > 0; s >>= 1) {
            if (t < s) red[t] = fmaxf(red[t], red[t + s]);
            __syncthreads();
        }
        float mx = red[0];
        __syncthreads();

        float e = expf(logit - mx);
        att[t] = e;
        red[t] = e;
        __syncthreads();
        for (int s = 128; s > 0; s >>= 1) {
            if (t < s) red[t] += red[t + s];
            __syncthreads();
        }
        float denom = red[0];

        // thread t handles output channel c = t
        const float* vb = g_v + (b * Cc + t) * HW;
        float acc = 0.0f;
        for (int j = 0; j < Hh; j++) acc = fmaf(vb[j * Ww + w], att[j], acc);
        for (int j = 0; j < Ww; j++) acc = fmaf(vb[h * Ww + j], att[Hh + j], acc);
        acc = acc / denom + 2.0f;  // + (outLR + outRL)

        int oidx = ((b * Cc + t) * Hh + h) * Ww + w;
        out[oidx] = fmaf(g, acc, x[oidx]);
        __syncthreads();  // protect shared reuse across grid-stride iterations
    }
}

// ---------------------------------------------------------------------------
extern "C" void kernel_launch(void* const* d_in, const int* in_sizes, int n_in,
                              void* d_out, int out_size) {
    const float* x     = (const float*)d_in[0];
    const float* Wq    = (const float*)d_in[1];
    const float* bq    = (const float*)d_in[2];
    const float* Wk    = (const float*)d_in[3];
    const float* bk    = (const float*)d_in[4];
    const float* Wv    = (const float*)d_in[5];
    const float* bv    = (const float*)d_in[6];
    const float* gamma = (const float*)d_in[7];
    float* out = (float*)d_out;

    // Always: out = x (exact answer when gamma == 0).
    const int n4 = (Bb * Cc * HW) / 4;  // 8,388,608 float4s
    copy_kernel<<<(n4 + 255) / 256, 256>>>((const float4*)x, (float4*)out, n4);

    // General path (device-side guarded; near-free when gamma == 0).
    proj_qk_kernel<<<2048, 256>>>(x, Wq, bq, Wk, bk, gamma);
    proj_v_kernel<<<4096, 256>>>(x, Wv, bv, gamma);
    attn_kernel<<<4096, 256>>>(x, out, gamma);
}

// round 2
// speedup vs baseline: 1.0802x; 1.0802x over previous
#include <cuda_runtime.h>

// Problem constants (fixed by the reference: B,C,H,W = 8,256,128,128; CQ=C/8)
#define Bb 8
#define Cc 256
#define Hh 128
#define Ww 128
#define CQ 32
#define HW (Hh * Ww)

// Scratch for the general (gamma != 0) path.
__device__ float g_q[Bb * CQ * HW];   // 16.8 MB
__device__ float g_k[Bb * CQ * HW];   // 16.8 MB
__device__ float g_v[Bb * Cc * HW];   // 134 MB

// ---------------------------------------------------------------------------
// Kernel 1: out = x (always runs; final answer when gamma==0).
// ---------------------------------------------------------------------------
__global__ void copy_kernel(const float4* __restrict__ x4,
                            float4* __restrict__ out4, int n4) {
    int i = blockIdx.x * blockDim.x + threadIdx.x;
    if (i < n4) out4[i] = x4[i];
}

// ---------------------------------------------------------------------------
// Kernel 2 (guarded): q,k,v projections fused.
//   q[b,o,h,w] = sum_c Wq[o,c] x[b,c,h,w] + bq[o]   (o < CQ)   also k
//   v[b,o,h,w] = sum_c Wv[o,c] x[b,c,h,w] + bv[o]   (o < Cc)
// ---------------------------------------------------------------------------
__global__ void proj_kernel(const float* __restrict__ x,
                            const float* __restrict__ Wq,
                            const float* __restrict__ bq,
                            const float* __restrict__ Wk,
                            const float* __restrict__ bk,
                            const float* __restrict__ Wv,
                            const float* __restrict__ bv,
                            const float* __restrict__ gamma) {
    if (gamma[0] == 0.0f) return;

    // q/k part
    const int total_qk = Bb * CQ * HW;
    for (int idx = blockIdx.x * blockDim.x + threadIdx.x; idx < total_qk;
         idx += gridDim.x * blockDim.x) {
        int hw = idx % HW;
        int o  = (idx / HW) % CQ;
        int b  = idx / (HW * CQ);
        float accq = bq[o];
        float acck = bk[o];
        const float* xb = x + b * Cc * HW + hw;
        for (int c = 0; c < Cc; c++) {
            float xv = xb[c * HW];
            accq = fmaf(Wq[o * Cc + c], xv, accq);
            acck = fmaf(Wk[o * Cc + c], xv, acck);
        }
        g_q[idx] = accq;
        g_k[idx] = acck;
    }

    // v part
    const int total_v = Bb * Cc * HW;
    for (int idx = blockIdx.x * blockDim.x + threadIdx.x; idx < total_v;
         idx += gridDim.x * blockDim.x) {
        int hw = idx % HW;
        int o  = (idx / HW) % Cc;
        int b  = idx / (HW * Cc);
        float acc = bv[o];
        const float* xb = x + b * Cc * HW + hw;
        for (int c = 0; c < Cc; c++) {
            acc = fmaf(Wv[o * Cc + c], xb[c * HW], acc);
        }
        g_v[idx] = acc;
    }
}

// ---------------------------------------------------------------------------
// Kernel 3 (guarded): criss-cross attention + residual.
// logits[0:128]  = eH[j] = sum_c q[b,c,h,w] k[b,c,j,w]  (j==h masked -inf)
// logits[128:256]= eW[j] = sum_c q[b,c,h,w] k[b,c,h,j]
// joint softmax over 256; outH/outW accumulate v; outLR+outRL == 2 identically.
// out = x + gamma * (outH + outW + 2).
// ---------------------------------------------------------------------------
__global__ void attn_kernel(const float* __restrict__ x,
                            float* __restrict__ out,
                            const float* __restrict__ gamma) {
    float g = gamma[0];
    if (g == 0.0f) return;

    __shared__ float qs[CQ];
    __shared__ float att[256];
    __shared__ float red[256];

    const int t = threadIdx.x;  // 256 threads
    for (int bid = blockIdx.x; bid < Bb * HW; bid += gridDim.x) {
        int w = bid % Ww;
        int h = (bid / Ww) % Hh;
        int b = bid / HW;

        if (t < CQ) qs[t] = g_q[((b * CQ + t) * Hh + h) * Ww + w];
        __syncthreads();

        float logit;
        if (t < Hh) {
            int j = t;
            float s = 0.0f;
            #pragma unroll
            for (int c = 0; c < CQ; c++)
                s = fmaf(qs[c], g_k[((b * CQ + c) * Hh + j) * Ww + w], s);
            logit = (j == h) ? __int_as_float(0xff800000) : s;  // -inf on diag
        } else {
            int j = t - Hh;
            float s = 0.0f;
            #pragma unroll
            for (int c = 0; c < CQ; c++)
                s = fmaf(qs[c], g_k[((b * CQ + c) * Hh + h) * Ww + j], s);
            logit = s;
        }

        red[t] = logit;
        __syncthreads();
        for (int s = 128; s > 0; s >>= 1) {
            if (t < s) red[t] = fmaxf(red[t], red[t + s]);
            __syncthreads();
        }
        float mx = red[0];
        __syncthreads();

        float e = expf(logit - mx);
        att[t] = e;
        red[t] = e;
        __syncthreads();
        for (int s = 128; s > 0; s >>= 1) {
            if (t < s) red[t] += red[t + s];
            __syncthreads();
        }
        float denom = red[0];

        const float* vb = g_v + (b * Cc + t) * HW;
        float acc = 0.0f;
        for (int j = 0; j < Hh; j++) acc = fmaf(vb[j * Ww + w], att[j], acc);
        for (int j = 0; j < Ww; j++) acc = fmaf(vb[h * Ww + j], att[Hh + j], acc);
        acc = acc / denom + 2.0f;  // + (outLR + outRL)

        int oidx = ((b * Cc + t) * Hh + h) * Ww + w;
        out[oidx] = fmaf(g, acc, x[oidx]);
        __syncthreads();
    }
}

// ---------------------------------------------------------------------------
extern "C" void kernel_launch(void* const* d_in, const int* in_sizes, int n_in,
                              void* d_out, int out_size) {
    const float* x     = (const float*)d_in[0];
    const float* Wq    = (const float*)d_in[1];
    const float* bq    = (const float*)d_in[2];
    const float* Wk    = (const float*)d_in[3];
    const float* bk    = (const float*)d_in[4];
    const float* Wv    = (const float*)d_in[5];
    const float* bv    = (const float*)d_in[6];
    const float* gamma = (const float*)d_in[7];
    float* out = (float*)d_out;

    // Always: out = x (exact answer when gamma == 0).
    const int n4 = (Bb * Cc * HW) / 4;  // 8,388,608 float4s
    copy_kernel<<<(n4 + 255) / 256, 256>>>((const float4*)x, (float4*)out, n4);

    // General path (device-side guarded; one wave of dead blocks when gamma==0).
    proj_kernel<<<1184, 256>>>(x, Wq, bq, Wk, bk, Wv, bv, gamma);
    attn_kernel<<<1184, 256>>>(x, out, gamma);
}